// round 2
// baseline (speedup 1.0000x reference)
#include <cuda_runtime.h>
#include <math.h>

#define V 50257
#define H 1024
#define L 128

// ---------------- scratch (device globals) ----------------
__device__ float g_attn_logits[L];
__device__ float g_attn_applied[H];
__device__ float g_x[H];
__device__ float g_gi0[3 * H];
__device__ float g_gh0[3 * H];
__device__ float g_gi1[3 * H];
__device__ float g_gh1[3 * H];
__device__ float g_h0[H];
__device__ float g_h1[H];
__device__ float g_red_max[128];
__device__ float g_red_sum[128];

// ---------------- reduction helpers ----------------
__inline__ __device__ float warpReduceSum(float v) {
    #pragma unroll
    for (int o = 16; o > 0; o >>= 1) v += __shfl_down_sync(0xffffffffu, v, o);
    return v;
}
__inline__ __device__ float warpReduceMax(float v) {
    #pragma unroll
    for (int o = 16; o > 0; o >>= 1) v = fmaxf(v, __shfl_down_sync(0xffffffffu, v, o));
    return v;
}
__inline__ __device__ float blockReduceSum(float v, float* sh) {
    int lane = threadIdx.x & 31, wid = threadIdx.x >> 5;
    v = warpReduceSum(v);
    if (lane == 0) sh[wid] = v;
    __syncthreads();
    int nw = blockDim.x >> 5;
    v = (threadIdx.x < nw) ? sh[lane] : 0.f;
    if (wid == 0) v = warpReduceSum(v);
    return v;
}
__inline__ __device__ float blockReduceMax(float v, float* sh) {
    int lane = threadIdx.x & 31, wid = threadIdx.x >> 5;
    v = warpReduceMax(v);
    if (lane == 0) sh[wid] = v;
    __syncthreads();
    int nw = blockDim.x >> 5;
    v = (threadIdx.x < nw) ? sh[lane] : -INFINITY;
    if (wid == 0) v = warpReduceMax(v);
    return v;
}

__inline__ __device__ float dot4(float4 a, float4 b) {
    return a.x * b.x + a.y * b.y + a.z * b.z + a.w * b.w;
}

// ---------------- K1: fused attn_logits + gh0 + gh1 -------------------------
// grid = L + 3H + 3H = 6272, block = 256
__global__ void k_phase1(const long long* __restrict__ ids,
                         const float* __restrict__ emb,
                         const float* __restrict__ hidden,
                         const float* __restrict__ attn_w,
                         const float* __restrict__ attn_b,
                         const float* __restrict__ w_hh0,
                         const float* __restrict__ b_hh0,
                         const float* __restrict__ w_hh1,
                         const float* __restrict__ b_hh1) {
    __shared__ float sh[32];
    int b = blockIdx.x;
    int t = threadIdx.x;  // 256, one float4 = 1024 floats per pass
    if (b < L) {
        // attention logit row b: dot over [embedded(H), hidden0(H)]
        const float4* er = (const float4*)(emb + (size_t)ids[0] * H);
        const float4* h0 = (const float4*)hidden;
        const float4* w  = (const float4*)(attn_w + (size_t)b * (2 * H));
        float s = dot4(w[t], er[t]) + dot4(w[t + 256], h0[t]);
        s = blockReduceSum(s, sh);
        if (t == 0) g_attn_logits[b] = s + attn_b[b];
    } else if (b < L + 3 * H) {
        int j = b - L;
        const float4* w = (const float4*)(w_hh0 + (size_t)j * H);
        const float4* h = (const float4*)hidden;
        float s = dot4(w[t], h[t]);
        s = blockReduceSum(s, sh);
        if (t == 0) g_gh0[j] = s + b_hh0[j];
    } else {
        int j = b - L - 3 * H;
        const float4* w = (const float4*)(w_hh1 + (size_t)j * H);
        const float4* h = (const float4*)(hidden + H);
        float s = dot4(w[t], h[t]);
        s = blockReduceSum(s, sh);
        if (t == 0) g_gh1[j] = s + b_hh1[j];
    }
}

// ---------------- K2: softmax (redundant per block) + attn_applied ----------
// grid = 8, block = 128
__global__ void k_softmax_applied(const float* __restrict__ enc,
                                  float* __restrict__ out) {
    __shared__ float sh[32];
    __shared__ float sM, sS;
    __shared__ float aw[L];
    int t = threadIdx.x;  // 128
    float v = g_attn_logits[t];
    float m = blockReduceMax(v, sh);
    if (t == 0) sM = m;
    __syncthreads();
    float e = expf(v - sM);
    __syncthreads();
    float s = blockReduceSum(e, sh);
    if (t == 0) sS = s;
    __syncthreads();
    float w = e / sS;
    aw[t] = w;
    if (blockIdx.x == 0) out[V + 2 * H + t] = w;
    __syncthreads();
    int h = blockIdx.x * 128 + t;
    float acc = 0.f;
    #pragma unroll 8
    for (int l = 0; l < L; l++) acc += aw[l] * enc[(size_t)l * H + h];
    g_attn_applied[h] = acc;
}

// ---------------- K3: comb + relu -> x ---------------------------------------
// grid = H (1024), block = 512; thread handles one float4 of the 2H input
__global__ void k_comb(const long long* __restrict__ ids,
                       const float* __restrict__ emb,
                       const float* __restrict__ comb_w,
                       const float* __restrict__ comb_b) {
    __shared__ float sh[32];
    int j = blockIdx.x;
    int t = threadIdx.x;  // 512, one float4 = 2048 floats
    const float4* w = (const float4*)(comb_w + (size_t)j * (2 * H));
    float4 in;
    if (t < 256) in = ((const float4*)(emb + (size_t)ids[0] * H))[t];
    else         in = ((const float4*)g_attn_applied)[t - 256];
    float s = dot4(w[t], in);
    s = blockReduceSum(s, sh);
    if (t == 0) {
        float r = s + comb_b[j];
        g_x[j] = r > 0.f ? r : 0.f;
    }
}

// ---------------- K4/K6: gi = x @ w_ih^T + b_ih --------------------------------
// grid = 3H, block = 256
__global__ void k_gi(const float* __restrict__ xin,
                     const float* __restrict__ w_ih,
                     const float* __restrict__ b_ih,
                     float* __restrict__ gi) {
    __shared__ float sh[32];
    int j = blockIdx.x;
    int t = threadIdx.x;
    const float4* w = (const float4*)(w_ih + (size_t)j * H);
    const float4* x = (const float4*)xin;
    float s = dot4(w[t], x[t]);
    s = blockReduceSum(s, sh);
    if (t == 0) gi[j] = s + b_ih[j];
}

// ---------------- K5/K7: GRU combine -------------------------------------------
// grid = 1, block = 1024
__global__ void k_combine(const float* __restrict__ gi,
                          const float* __restrict__ gh,
                          const float* __restrict__ hprev,
                          float* __restrict__ hnew,
                          float* __restrict__ out_hid) {
    int t = threadIdx.x;
    float r = 1.f / (1.f + expf(-(gi[t] + gh[t])));
    float z = 1.f / (1.f + expf(-(gi[H + t] + gh[H + t])));
    float n = tanhf(gi[2 * H + t] + r * gh[2 * H + t]);
    float h = (1.f - z) * n + z * hprev[t];
    hnew[t] = h;
    out_hid[t] = h;
}

// ---------------- K8: logits = h1 @ out_w^T + b --------------------------------
// one warp per row, 8 warps/block
__global__ void k_logits(const float* __restrict__ out_w,
                         const float* __restrict__ out_b,
                         float* __restrict__ logits) {
    int warp = threadIdx.x >> 5;
    int lane = threadIdx.x & 31;
    int j = blockIdx.x * 8 + warp;
    if (j >= V) return;
    const float4* w = (const float4*)(out_w + (size_t)j * H);
    const float4* h = (const float4*)g_h1;
    float s = 0.f;
    #pragma unroll
    for (int i = 0; i < 8; i++) {
        int idx = i * 32 + lane;
        s += dot4(w[idx], h[idx]);
    }
    s = warpReduceSum(s);
    if (lane == 0) logits[j] = s + out_b[j];
}

// ---------------- K9: per-block max/sumexp partials -----------------------------
#define RED_BLOCKS 128
__global__ void k_lse_partial(const float* __restrict__ logits) {
    __shared__ float sh[32];
    __shared__ float sM;
    const int chunk = (V + RED_BLOCKS - 1) / RED_BLOCKS;  // 393
    int start = blockIdx.x * chunk;
    int end = min(start + chunk, V);
    float m = -INFINITY;
    for (int i = start + threadIdx.x; i < end; i += blockDim.x)
        m = fmaxf(m, logits[i]);
    m = blockReduceMax(m, sh);
    if (threadIdx.x == 0) sM = m;
    __syncthreads();
    float M = sM;
    float s = 0.f;
    for (int i = start + threadIdx.x; i < end; i += blockDim.x)
        s += expf(logits[i] - M);
    __syncthreads();
    s = blockReduceSum(s, sh);
    if (threadIdx.x == 0) {
        g_red_max[blockIdx.x] = M;
        g_red_sum[blockIdx.x] = s;
    }
}

// ---------------- K10: reduce partials (redundant) + apply ------------------------
// grid = ceil(V/1024) = 50, block = 256; each thread applies 4 strided elements
__global__ void k_lse_apply(float* __restrict__ logits) {
    __shared__ float sh[32];
    __shared__ float sM, sLogZ;
    int t = threadIdx.x;
    float m = (t < RED_BLOCKS) ? g_red_max[t] : -INFINITY;
    float M = blockReduceMax(m, sh);
    if (t == 0) sM = M;
    __syncthreads();
    M = sM;
    float s = (t < RED_BLOCKS) ? g_red_sum[t] * expf(g_red_max[t] - M) : 0.f;
    __syncthreads();
    s = blockReduceSum(s, sh);
    if (t == 0) sLogZ = M + logf(s);
    __syncthreads();
    float lz = sLogZ;
    int base = blockIdx.x * 1024 + t;
    #pragma unroll
    for (int k = 0; k < 4; k++) {
        int i = base + k * 256;
        if (i < V) logits[i] -= lz;
    }
}

// =================================================================================
extern "C" void kernel_launch(void* const* d_in, const int* in_sizes, int n_in,
                              void* d_out, int out_size) {
    const long long* input_ids = (const long long*)d_in[0];
    const float* hidden  = (const float*)d_in[1];   // (2,1,H)
    const float* enc     = (const float*)d_in[2];   // (L,H)
    const float* emb     = (const float*)d_in[3];   // (V,H)
    const float* attn_w  = (const float*)d_in[4];   // (L,2H)
    const float* attn_b  = (const float*)d_in[5];
    const float* comb_w  = (const float*)d_in[6];   // (H,2H)
    const float* comb_b  = (const float*)d_in[7];
    const float* w_ih0   = (const float*)d_in[8];
    const float* w_hh0   = (const float*)d_in[9];
    const float* b_ih0   = (const float*)d_in[10];
    const float* b_hh0   = (const float*)d_in[11];
    const float* w_ih1   = (const float*)d_in[12];
    const float* w_hh1   = (const float*)d_in[13];
    const float* b_ih1   = (const float*)d_in[14];
    const float* b_hh1   = (const float*)d_in[15];
    const float* out_w   = (const float*)d_in[16];  // (V,H)
    const float* out_b   = (const float*)d_in[17];

    float* out = (float*)d_out;
    // layout: [0,V) log_softmax, [V,V+H) h0, [V+H,V+2H) h1, [V+2H,V+2H+L) attn_w

    const float* h0_prev = hidden;
    const float* h1_prev = hidden + H;

    float* p_x;   cudaGetSymbolAddress((void**)&p_x, g_x);
    float* p_h0;  cudaGetSymbolAddress((void**)&p_h0, g_h0);
    float* p_h1;  cudaGetSymbolAddress((void**)&p_h1, g_h1);
    float* p_gi0; cudaGetSymbolAddress((void**)&p_gi0, g_gi0);
    float* p_gh0; cudaGetSymbolAddress((void**)&p_gh0, g_gh0);
    float* p_gi1; cudaGetSymbolAddress((void**)&p_gi1, g_gi1);
    float* p_gh1; cudaGetSymbolAddress((void**)&p_gh1, g_gh1);

    // Phase 1: attention logits + both hidden-side GRU gate GEMVs (independent)
    k_phase1<<<L + 6 * H, 256>>>(input_ids, emb, hidden, attn_w, attn_b,
                                 w_hh0, b_hh0, w_hh1, b_hh1);
    // softmax + attention context
    k_softmax_applied<<<8, 128>>>(enc, out);
    // comb + relu
    k_comb<<<H, 512>>>(input_ids, emb, comb_w, comb_b);
    // GRU layer 0
    k_gi<<<3 * H, 256>>>(p_x, w_ih0, b_ih0, p_gi0);
    k_combine<<<1, H>>>(p_gi0, p_gh0, h0_prev, p_h0, out + V);
    // GRU layer 1
    k_gi<<<3 * H, 256>>>(p_h0, w_ih1, b_ih1, p_gi1);
    k_combine<<<1, H>>>(p_gi1, p_gh1, h1_prev, p_h1, out + V + H);
    // output projection + log_softmax
    k_logits<<<(V + 7) / 8, 256>>>(out_w, out_b, out);
    k_lse_partial<<<RED_BLOCKS, 256>>>(out);
    k_lse_apply<<<(V + 1023) / 1024, 256>>>(out);
}

// round 3
// speedup vs baseline: 1.0736x; 1.0736x over previous
#include <cuda_runtime.h>
#include <math.h>

#define V 50257
#define H 1024
#define L 128

// ---------------- scratch (device globals; zero-initialized) ----------------
__device__ float g_attn_logits[L];
__device__ float g_attn_applied[H];
__device__ float g_x[H];
__device__ float g_gi0[3 * H];
__device__ float g_gh0[3 * H];
__device__ float g_gi1[3 * H];
__device__ float g_gh1[3 * H];
__device__ float g_h0[H];
__device__ float g_h1[H];
__device__ float g_red_max[128];
__device__ float g_red_sum[128];
__device__ unsigned int g_ctr0;   // zero-init; self-resetting
__device__ unsigned int g_ctr1;

// ---------------- reduction helpers ----------------
__inline__ __device__ float warpReduceSum(float v) {
    #pragma unroll
    for (int o = 16; o > 0; o >>= 1) v += __shfl_down_sync(0xffffffffu, v, o);
    return v;
}
__inline__ __device__ float warpReduceMax(float v) {
    #pragma unroll
    for (int o = 16; o > 0; o >>= 1) v = fmaxf(v, __shfl_down_sync(0xffffffffu, v, o));
    return v;
}
__inline__ __device__ float blockReduceSum(float v, float* sh) {
    int lane = threadIdx.x & 31, wid = threadIdx.x >> 5;
    v = warpReduceSum(v);
    if (lane == 0) sh[wid] = v;
    __syncthreads();
    int nw = blockDim.x >> 5;
    v = (threadIdx.x < nw) ? sh[lane] : 0.f;
    if (wid == 0) v = warpReduceSum(v);
    return v;
}
__inline__ __device__ float blockReduceMax(float v, float* sh) {
    int lane = threadIdx.x & 31, wid = threadIdx.x >> 5;
    v = warpReduceMax(v);
    if (lane == 0) sh[wid] = v;
    __syncthreads();
    int nw = blockDim.x >> 5;
    v = (threadIdx.x < nw) ? sh[lane] : -INFINITY;
    if (wid == 0) v = warpReduceMax(v);
    return v;
}
__inline__ __device__ float dot4(float4 a, float4 b) {
    return a.x * b.x + a.y * b.y + a.z * b.z + a.w * b.w;
}

// ---------------- K1: fused attn_logits + gh0 + gh1 (warp-per-row) ----------
// rows: [0,128) attn, [128,128+3072) gh0, [...) gh1. 8 warps/block -> 784 blocks.
__global__ void k_phase1(const long long* __restrict__ ids,
                         const float* __restrict__ emb,
                         const float* __restrict__ hidden,
                         const float* __restrict__ attn_w,
                         const float* __restrict__ attn_b,
                         const float* __restrict__ w_hh0,
                         const float* __restrict__ b_hh0,
                         const float* __restrict__ w_hh1,
                         const float* __restrict__ b_hh1) {
    int warp = threadIdx.x >> 5, lane = threadIdx.x & 31;
    int row = blockIdx.x * 8 + warp;
    if (row < L) {
        const float4* er = (const float4*)(emb + (size_t)ids[0] * H);
        const float4* h0 = (const float4*)hidden;
        const float4* w  = (const float4*)(attn_w + (size_t)row * (2 * H));
        float s = 0.f;
        #pragma unroll
        for (int i = 0; i < 8; i++) {
            int idx = lane + 32 * i;
            s += dot4(__ldcs(&w[idx]), er[idx]);
            s += dot4(__ldcs(&w[idx + 256]), h0[idx]);
        }
        s = warpReduceSum(s);
        if (lane == 0) g_attn_logits[row] = s + attn_b[row];
    } else if (row < L + 3 * H) {
        int j = row - L;
        const float4* w = (const float4*)(w_hh0 + (size_t)j * H);
        const float4* h = (const float4*)hidden;
        float s = 0.f;
        #pragma unroll
        for (int i = 0; i < 8; i++) {
            int idx = lane + 32 * i;
            s += dot4(__ldcs(&w[idx]), h[idx]);
        }
        s = warpReduceSum(s);
        if (lane == 0) g_gh0[j] = s + b_hh0[j];
    } else {
        int j = row - L - 3 * H;
        const float4* w = (const float4*)(w_hh1 + (size_t)j * H);
        const float4* h = (const float4*)(hidden + H);
        float s = 0.f;
        #pragma unroll
        for (int i = 0; i < 8; i++) {
            int idx = lane + 32 * i;
            s += dot4(__ldcs(&w[idx]), h[idx]);
        }
        s = warpReduceSum(s);
        if (lane == 0) g_gh1[j] = s + b_hh1[j];
    }
}

// ---------------- K2: softmax (redundant per block) + attn_applied ----------
__global__ void k_softmax_applied(const float* __restrict__ enc,
                                  float* __restrict__ out) {
    __shared__ float sh[32];
    __shared__ float sM, sS;
    __shared__ float aw[L];
    int t = threadIdx.x;  // 128
    float v = g_attn_logits[t];
    float m = blockReduceMax(v, sh);
    if (t == 0) sM = m;
    __syncthreads();
    float e = expf(v - sM);
    __syncthreads();
    float s = blockReduceSum(e, sh);
    if (t == 0) sS = s;
    __syncthreads();
    float w = e / sS;
    aw[t] = w;
    if (blockIdx.x == 0) out[V + 2 * H + t] = w;
    __syncthreads();
    int h = blockIdx.x * 128 + t;
    float acc = 0.f;
    #pragma unroll 8
    for (int l = 0; l < L; l++) acc += aw[l] * enc[(size_t)l * H + h];
    g_attn_applied[h] = acc;
}

// ---------------- K3: comb + relu -> x (warp-per-row) -----------------------
// 1024 rows of width 2H; 8 warps/block -> 128 blocks
__global__ void k_comb(const long long* __restrict__ ids,
                       const float* __restrict__ emb,
                       const float* __restrict__ comb_w,
                       const float* __restrict__ comb_b) {
    int warp = threadIdx.x >> 5, lane = threadIdx.x & 31;
    int j = blockIdx.x * 8 + warp;
    const float4* er = (const float4*)(emb + (size_t)ids[0] * H);
    const float4* ap = (const float4*)g_attn_applied;
    const float4* w  = (const float4*)(comb_w + (size_t)j * (2 * H));
    float s = 0.f;
    #pragma unroll
    for (int i = 0; i < 8; i++) {
        int idx = lane + 32 * i;
        s += dot4(__ldcs(&w[idx]), er[idx]);
        s += dot4(__ldcs(&w[idx + 256]), ap[idx]);
    }
    s = warpReduceSum(s);
    if (lane == 0) {
        float r = s + comb_b[j];
        g_x[j] = r > 0.f ? r : 0.f;
    }
}

// ---------------- K4/K5: gi GEMV + fused last-block GRU combine -------------
// 3072 rows of width H; 8 warps/block -> 384 blocks
__global__ void k_gi_combine(const float* __restrict__ xin,
                             const float* __restrict__ w_ih,
                             const float* __restrict__ b_ih,
                             float* __restrict__ gi,
                             const float* __restrict__ gh,
                             const float* __restrict__ hprev,
                             float* __restrict__ hnew,
                             float* __restrict__ out_hid,
                             unsigned int* __restrict__ ctr) {
    int warp = threadIdx.x >> 5, lane = threadIdx.x & 31;
    int row = blockIdx.x * 8 + warp;
    const float4* w = (const float4*)(w_ih + (size_t)row * H);
    const float4* x = (const float4*)xin;
    float s = 0.f;
    #pragma unroll
    for (int i = 0; i < 8; i++) {
        int idx = lane + 32 * i;
        s += dot4(__ldcs(&w[idx]), x[idx]);
    }
    s = warpReduceSum(s);
    if (lane == 0) gi[row] = s + b_ih[row];

    // last block performs the GRU gate combine
    __shared__ bool isLast;
    __threadfence();
    __syncthreads();
    if (threadIdx.x == 0) {
        unsigned int old = atomicAdd(ctr, 1u);
        isLast = (old == gridDim.x - 1);
        if (isLast) *ctr = 0;  // reset for next graph replay (all adds done)
    }
    __syncthreads();
    if (isLast) {
        __threadfence();
        for (int t = threadIdx.x; t < H; t += blockDim.x) {
            float r = 1.f / (1.f + expf(-(gi[t] + gh[t])));
            float z = 1.f / (1.f + expf(-(gi[H + t] + gh[H + t])));
            float n = tanhf(gi[2 * H + t] + r * gh[2 * H + t]);
            float h = (1.f - z) * n + z * hprev[t];
            hnew[t] = h;
            out_hid[t] = h;
        }
    }
}

// ---------------- K6: logits = h1 @ out_w^T + b (2 rows per warp) ------------
// 8 warps/block, 2 adjacent rows per warp -> ceil(V/16) = 3142 blocks
__global__ void k_logits(const float* __restrict__ out_w,
                         const float* __restrict__ out_b,
                         float* __restrict__ logits) {
    int warp = threadIdx.x >> 5;
    int lane = threadIdx.x & 31;
    int j0 = (blockIdx.x * 8 + warp) * 2;
    if (j0 >= V) return;
    const float4* h = (const float4*)g_h1;
    float4 hv[8];
    #pragma unroll
    for (int i = 0; i < 8; i++) hv[i] = h[lane + 32 * i];

    const float4* w0 = (const float4*)(out_w + (size_t)j0 * H);
    float s0 = 0.f;
    #pragma unroll
    for (int i = 0; i < 8; i++) s0 += dot4(__ldcs(&w0[lane + 32 * i]), hv[i]);
    s0 = warpReduceSum(s0);
    if (lane == 0) logits[j0] = s0 + out_b[j0];

    int j1 = j0 + 1;
    if (j1 < V) {
        const float4* w1 = (const float4*)(out_w + (size_t)j1 * H);
        float s1 = 0.f;
        #pragma unroll
        for (int i = 0; i < 8; i++) s1 += dot4(__ldcs(&w1[lane + 32 * i]), hv[i]);
        s1 = warpReduceSum(s1);
        if (lane == 0) logits[j1] = s1 + out_b[j1];
    }
}

// ---------------- K7: per-block max/sumexp partials --------------------------
#define RED_BLOCKS 128
__global__ void k_lse_partial(const float* __restrict__ logits) {
    __shared__ float sh[32];
    __shared__ float sM;
    const int chunk = (V + RED_BLOCKS - 1) / RED_BLOCKS;  // 393
    int start = blockIdx.x * chunk;
    int end = min(start + chunk, V);
    float m = -INFINITY;
    for (int i = start + threadIdx.x; i < end; i += blockDim.x)
        m = fmaxf(m, logits[i]);
    m = blockReduceMax(m, sh);
    if (threadIdx.x == 0) sM = m;
    __syncthreads();
    float M = sM;
    float s = 0.f;
    for (int i = start + threadIdx.x; i < end; i += blockDim.x)
        s += expf(logits[i] - M);
    __syncthreads();
    s = blockReduceSum(s, sh);
    if (threadIdx.x == 0) {
        g_red_max[blockIdx.x] = M;
        g_red_sum[blockIdx.x] = s;
    }
}

// ---------------- K8: reduce partials (redundant) + apply --------------------
__global__ void k_lse_apply(float* __restrict__ logits) {
    __shared__ float sh[32];
    __shared__ float sM, sLogZ;
    int t = threadIdx.x;
    float m = (t < RED_BLOCKS) ? g_red_max[t] : -INFINITY;
    float M = blockReduceMax(m, sh);
    if (t == 0) sM = M;
    __syncthreads();
    M = sM;
    float s = (t < RED_BLOCKS) ? g_red_sum[t] * expf(g_red_max[t] - M) : 0.f;
    __syncthreads();
    s = blockReduceSum(s, sh);
    if (t == 0) sLogZ = M + logf(s);
    __syncthreads();
    float lz = sLogZ;
    int base = blockIdx.x * 1024 + t;
    #pragma unroll
    for (int k = 0; k < 4; k++) {
        int i = base + k * 256;
        if (i < V) logits[i] -= lz;
    }
}

// =================================================================================
extern "C" void kernel_launch(void* const* d_in, const int* in_sizes, int n_in,
                              void* d_out, int out_size) {
    const long long* input_ids = (const long long*)d_in[0];
    const float* hidden  = (const float*)d_in[1];
    const float* enc     = (const float*)d_in[2];
    const float* emb     = (const float*)d_in[3];
    const float* attn_w  = (const float*)d_in[4];
    const float* attn_b  = (const float*)d_in[5];
    const float* comb_w  = (const float*)d_in[6];
    const float* comb_b  = (const float*)d_in[7];
    const float* w_ih0   = (const float*)d_in[8];
    const float* w_hh0   = (const float*)d_in[9];
    const float* b_ih0   = (const float*)d_in[10];
    const float* b_hh0   = (const float*)d_in[11];
    const float* w_ih1   = (const float*)d_in[12];
    const float* w_hh1   = (const float*)d_in[13];
    const float* b_ih1   = (const float*)d_in[14];
    const float* b_hh1   = (const float*)d_in[15];
    const float* out_w   = (const float*)d_in[16];
    const float* out_b   = (const float*)d_in[17];

    float* out = (float*)d_out;

    const float* h0_prev = hidden;
    const float* h1_prev = hidden + H;

    float* p_x;   cudaGetSymbolAddress((void**)&p_x, g_x);
    float* p_h0;  cudaGetSymbolAddress((void**)&p_h0, g_h0);
    float* p_h1;  cudaGetSymbolAddress((void**)&p_h1, g_h1);
    float* p_gi0; cudaGetSymbolAddress((void**)&p_gi0, g_gi0);
    float* p_gh0; cudaGetSymbolAddress((void**)&p_gh0, g_gh0);
    float* p_gi1; cudaGetSymbolAddress((void**)&p_gi1, g_gi1);
    float* p_gh1; cudaGetSymbolAddress((void**)&p_gh1, g_gh1);
    unsigned int* p_c0; cudaGetSymbolAddress((void**)&p_c0, g_ctr0);
    unsigned int* p_c1; cudaGetSymbolAddress((void**)&p_c1, g_ctr1);

    // Phase 1: attention logits + both hidden-side GRU gate GEMVs
    k_phase1<<<(L + 6 * H) / 8, 256>>>(input_ids, emb, hidden, attn_w, attn_b,
                                       w_hh0, b_hh0, w_hh1, b_hh1);
    // softmax + attention context
    k_softmax_applied<<<8, 128>>>(enc, out);
    // comb + relu
    k_comb<<<H / 8, 256>>>(input_ids, emb, comb_w, comb_b);
    // GRU layer 0 (gi GEMV + fused combine)
    k_gi_combine<<<3 * H / 8, 256>>>(p_x, w_ih0, b_ih0, p_gi0, p_gh0,
                                     h0_prev, p_h0, out + V, p_c0);
    // GRU layer 1
    k_gi_combine<<<3 * H / 8, 256>>>(p_h0, w_ih1, b_ih1, p_gi1, p_gh1,
                                     h1_prev, p_h1, out + V + H, p_c1);
    // output projection + log_softmax
    k_logits<<<(V + 15) / 16, 256>>>(out_w, out_b, out);
    k_lse_partial<<<RED_BLOCKS, 256>>>(out);
    k_lse_apply<<<(V + 1023) / 1024, 256>>>(out);
}

// round 4
// speedup vs baseline: 1.1946x; 1.1128x over previous
#include <cuda_runtime.h>
#include <math.h>

#define V 50257
#define H 1024
#define L 128

// ---------------- scratch (device globals) ----------------
__device__ float g_attn_logits[L];
__device__ float g_attn_applied[H];
__device__ float g_x[H];
__device__ float g_gi0[3 * H];
__device__ float g_gh0[3 * H];
__device__ float g_gi1[3 * H];
__device__ float g_gh1[3 * H];
__device__ float g_h0[H];
__device__ float g_h1[H];
__device__ float g_red_max[128];
__device__ float g_red_sum[128];

// ---------------- reduction helpers ----------------
__inline__ __device__ float warpReduceSum(float v) {
    #pragma unroll
    for (int o = 16; o > 0; o >>= 1) v += __shfl_down_sync(0xffffffffu, v, o);
    return v;
}
__inline__ __device__ float warpReduceMax(float v) {
    #pragma unroll
    for (int o = 16; o > 0; o >>= 1) v = fmaxf(v, __shfl_down_sync(0xffffffffu, v, o));
    return v;
}
__inline__ __device__ float blockReduceSum(float v, float* sh) {
    int lane = threadIdx.x & 31, wid = threadIdx.x >> 5;
    v = warpReduceSum(v);
    if (lane == 0) sh[wid] = v;
    __syncthreads();
    int nw = blockDim.x >> 5;
    v = (threadIdx.x < nw) ? sh[lane] : 0.f;
    if (wid == 0) v = warpReduceSum(v);
    return v;
}
__inline__ __device__ float blockReduceMax(float v, float* sh) {
    int lane = threadIdx.x & 31, wid = threadIdx.x >> 5;
    v = warpReduceMax(v);
    if (lane == 0) sh[wid] = v;
    __syncthreads();
    int nw = blockDim.x >> 5;
    v = (threadIdx.x < nw) ? sh[lane] : -INFINITY;
    if (wid == 0) v = warpReduceMax(v);
    return v;
}
__inline__ __device__ float dot4(float4 a, float4 b) {
    return a.x * b.x + a.y * b.y + a.z * b.z + a.w * b.w;
}

// batched 8x float4 dot: loads w into a register array FIRST (MLP=8+8)
__inline__ __device__ float dot_row_1024(const float4* __restrict__ w,
                                         const float4* __restrict__ x, int lane) {
    float4 wv[8], xv[8];
    #pragma unroll
    for (int i = 0; i < 8; i++) wv[i] = __ldcs(&w[lane + 32 * i]);
    #pragma unroll
    for (int i = 0; i < 8; i++) xv[i] = __ldg(&x[lane + 32 * i]);
    float s = 0.f;
    #pragma unroll
    for (int i = 0; i < 8; i++) s += dot4(wv[i], xv[i]);
    return s;
}

// ---------------- K1: fused attn_logits + gh0 + gh1 (warp-per-row) ----------
__global__ void __launch_bounds__(256) k_phase1(
        const long long* __restrict__ ids,
        const float* __restrict__ emb,
        const float* __restrict__ hidden,
        const float* __restrict__ attn_w,
        const float* __restrict__ attn_b,
        const float* __restrict__ w_hh0,
        const float* __restrict__ b_hh0,
        const float* __restrict__ w_hh1,
        const float* __restrict__ b_hh1) {
    int warp = threadIdx.x >> 5, lane = threadIdx.x & 31;
    int row = blockIdx.x * 8 + warp;
    if (row < L) {
        const float4* er = (const float4*)(emb + (size_t)ids[0] * H);
        const float4* h0 = (const float4*)hidden;
        const float4* w  = (const float4*)(attn_w + (size_t)row * (2 * H));
        float s = dot_row_1024(w, er, lane) + dot_row_1024(w + 256, h0, lane);
        s = warpReduceSum(s);
        if (lane == 0) g_attn_logits[row] = s + attn_b[row];
    } else if (row < L + 3 * H) {
        int j = row - L;
        float s = dot_row_1024((const float4*)(w_hh0 + (size_t)j * H),
                               (const float4*)hidden, lane);
        s = warpReduceSum(s);
        if (lane == 0) g_gh0[j] = s + b_hh0[j];
    } else {
        int j = row - L - 3 * H;
        float s = dot_row_1024((const float4*)(w_hh1 + (size_t)j * H),
                               (const float4*)(hidden + H), lane);
        s = warpReduceSum(s);
        if (lane == 0) g_gh1[j] = s + b_hh1[j];
    }
}

// ---------------- K2: softmax (redundant per block) + attn_applied ----------
__global__ void k_softmax_applied(const float* __restrict__ enc,
                                  float* __restrict__ out) {
    __shared__ float sh[32];
    __shared__ float sM, sS;
    __shared__ float aw[L];
    int t = threadIdx.x;  // 128
    float v = g_attn_logits[t];
    float m = blockReduceMax(v, sh);
    if (t == 0) sM = m;
    __syncthreads();
    float e = expf(v - sM);
    __syncthreads();
    float s = blockReduceSum(e, sh);
    if (t == 0) sS = s;
    __syncthreads();
    float w = e / sS;
    aw[t] = w;
    if (blockIdx.x == 0) out[V + 2 * H + t] = w;
    __syncthreads();
    int h = blockIdx.x * 128 + t;
    float acc = 0.f;
    #pragma unroll 8
    for (int l = 0; l < L; l++) acc += aw[l] * enc[(size_t)l * H + h];
    g_attn_applied[h] = acc;
}

// ---------------- K3: comb + relu -> x (warp-per-row, 2 batched passes) -----
__global__ void __launch_bounds__(256) k_comb(
        const long long* __restrict__ ids,
        const float* __restrict__ emb,
        const float* __restrict__ comb_w,
        const float* __restrict__ comb_b) {
    int warp = threadIdx.x >> 5, lane = threadIdx.x & 31;
    int j = blockIdx.x * 8 + warp;
    const float4* er = (const float4*)(emb + (size_t)ids[0] * H);
    const float4* ap = (const float4*)g_attn_applied;
    const float4* w  = (const float4*)(comb_w + (size_t)j * (2 * H));
    float s = dot_row_1024(w, er, lane) + dot_row_1024(w + 256, ap, lane);
    s = warpReduceSum(s);
    if (lane == 0) {
        float r = s + comb_b[j];
        g_x[j] = r > 0.f ? r : 0.f;
    }
}

// ---------------- K4/K6: gi = x @ w_ih^T + b_ih (warp-per-row, batched) -----
__global__ void __launch_bounds__(256) k_gi(
        const float* __restrict__ xin,
        const float* __restrict__ w_ih,
        const float* __restrict__ b_ih,
        float* __restrict__ gi) {
    int warp = threadIdx.x >> 5, lane = threadIdx.x & 31;
    int row = blockIdx.x * 8 + warp;
    float s = dot_row_1024((const float4*)(w_ih + (size_t)row * H),
                           (const float4*)xin, lane);
    s = warpReduceSum(s);
    if (lane == 0) gi[row] = s + b_ih[row];
}

// ---------------- K5/K7: GRU combine ------------------------------------------
__global__ void k_combine(const float* __restrict__ gi,
                          const float* __restrict__ gh,
                          const float* __restrict__ hprev,
                          float* __restrict__ hnew,
                          float* __restrict__ out_hid) {
    int t = threadIdx.x;
    float r = 1.f / (1.f + expf(-(gi[t] + gh[t])));
    float z = 1.f / (1.f + expf(-(gi[H + t] + gh[H + t])));
    float n = tanhf(gi[2 * H + t] + r * gh[2 * H + t]);
    float h = (1.f - z) * n + z * hprev[t];
    hnew[t] = h;
    out_hid[t] = h;
}

// ---------------- K8: logits (2 rows/warp, 16 batched loads) ------------------
__global__ void __launch_bounds__(256) k_logits(
        const float* __restrict__ out_w,
        const float* __restrict__ out_b,
        float* __restrict__ logits) {
    int warp = threadIdx.x >> 5;
    int lane = threadIdx.x & 31;
    int j0 = (blockIdx.x * 8 + warp) * 2;
    if (j0 >= V) return;
    const float4* h = (const float4*)g_h1;
    float4 hv[8];
    #pragma unroll
    for (int i = 0; i < 8; i++) hv[i] = __ldg(&h[lane + 32 * i]);

    const float4* w0 = (const float4*)(out_w + (size_t)j0 * H);
    bool has1 = (j0 + 1) < V;
    const float4* w1 = (const float4*)(out_w + (size_t)(has1 ? j0 + 1 : j0) * H);

    float4 w0v[8], w1v[8];
    #pragma unroll
    for (int i = 0; i < 8; i++) w0v[i] = __ldcs(&w0[lane + 32 * i]);
    #pragma unroll
    for (int i = 0; i < 8; i++) w1v[i] = __ldcs(&w1[lane + 32 * i]);

    float s0 = 0.f, s1 = 0.f;
    #pragma unroll
    for (int i = 0; i < 8; i++) {
        s0 += dot4(w0v[i], hv[i]);
        s1 += dot4(w1v[i], hv[i]);
    }
    s0 = warpReduceSum(s0);
    s1 = warpReduceSum(s1);
    if (lane == 0) {
        logits[j0] = s0 + out_b[j0];
        if (has1) logits[j0 + 1] = s1 + out_b[j0 + 1];
    }
}

// ---------------- K9: per-block max/sumexp partials ----------------------------
#define RED_BLOCKS 128
__global__ void k_lse_partial(const float* __restrict__ logits) {
    __shared__ float sh[32];
    __shared__ float sM;
    const int chunk = (V + RED_BLOCKS - 1) / RED_BLOCKS;  // 393
    int start = blockIdx.x * chunk;
    int end = min(start + chunk, V);
    float m = -INFINITY;
    for (int i = start + threadIdx.x; i < end; i += blockDim.x)
        m = fmaxf(m, logits[i]);
    m = blockReduceMax(m, sh);
    if (threadIdx.x == 0) sM = m;
    __syncthreads();
    float M = sM;
    float s = 0.f;
    for (int i = start + threadIdx.x; i < end; i += blockDim.x)
        s += expf(logits[i] - M);
    __syncthreads();
    s = blockReduceSum(s, sh);
    if (threadIdx.x == 0) {
        g_red_max[blockIdx.x] = M;
        g_red_sum[blockIdx.x] = s;
    }
}

// ---------------- K10: reduce partials (redundant) + apply ---------------------
__global__ void k_lse_apply(float* __restrict__ logits) {
    __shared__ float sh[32];
    __shared__ float sM, sLogZ;
    int t = threadIdx.x;
    float m = (t < RED_BLOCKS) ? g_red_max[t] : -INFINITY;
    float M = blockReduceMax(m, sh);
    if (t == 0) sM = M;
    __syncthreads();
    M = sM;
    float s = (t < RED_BLOCKS) ? g_red_sum[t] * expf(g_red_max[t] - M) : 0.f;
    __syncthreads();
    s = blockReduceSum(s, sh);
    if (t == 0) sLogZ = M + logf(s);
    __syncthreads();
    float lz = sLogZ;
    int base = blockIdx.x * 1024 + t;
    #pragma unroll
    for (int k = 0; k < 4; k++) {
        int i = base + k * 256;
        if (i < V) logits[i] -= lz;
    }
}

// =================================================================================
extern "C" void kernel_launch(void* const* d_in, const int* in_sizes, int n_in,
                              void* d_out, int out_size) {
    const long long* input_ids = (const long long*)d_in[0];
    const float* hidden  = (const float*)d_in[1];
    const float* enc     = (const float*)d_in[2];
    const float* emb     = (const float*)d_in[3];
    const float* attn_w  = (const float*)d_in[4];
    const float* attn_b  = (const float*)d_in[5];
    const float* comb_w  = (const float*)d_in[6];
    const float* comb_b  = (const float*)d_in[7];
    const float* w_ih0   = (const float*)d_in[8];
    const float* w_hh0   = (const float*)d_in[9];
    const float* b_ih0   = (const float*)d_in[10];
    const float* b_hh0   = (const float*)d_in[11];
    const float* w_ih1   = (const float*)d_in[12];
    const float* w_hh1   = (const float*)d_in[13];
    const float* b_ih1   = (const float*)d_in[14];
    const float* b_hh1   = (const float*)d_in[15];
    const float* out_w   = (const float*)d_in[16];
    const float* out_b   = (const float*)d_in[17];

    float* out = (float*)d_out;

    const float* h0_prev = hidden;
    const float* h1_prev = hidden + H;

    float* p_x;   cudaGetSymbolAddress((void**)&p_x, g_x);
    float* p_h0;  cudaGetSymbolAddress((void**)&p_h0, g_h0);
    float* p_h1;  cudaGetSymbolAddress((void**)&p_h1, g_h1);
    float* p_gi0; cudaGetSymbolAddress((void**)&p_gi0, g_gi0);
    float* p_gh0; cudaGetSymbolAddress((void**)&p_gh0, g_gh0);
    float* p_gi1; cudaGetSymbolAddress((void**)&p_gi1, g_gi1);
    float* p_gh1; cudaGetSymbolAddress((void**)&p_gh1, g_gh1);

    // Phase 1: attention logits + both hidden-side GRU gate GEMVs
    k_phase1<<<(L + 6 * H) / 8, 256>>>(input_ids, emb, hidden, attn_w, attn_b,
                                       w_hh0, b_hh0, w_hh1, b_hh1);
    // softmax + attention context
    k_softmax_applied<<<8, 128>>>(enc, out);
    // comb + relu
    k_comb<<<H / 8, 256>>>(input_ids, emb, comb_w, comb_b);
    // GRU layer 0
    k_gi<<<3 * H / 8, 256>>>(p_x, w_ih0, b_ih0, p_gi0);
    k_combine<<<1, H>>>(p_gi0, p_gh0, h0_prev, p_h0, out + V);
    // GRU layer 1
    k_gi<<<3 * H / 8, 256>>>(p_h0, w_ih1, b_ih1, p_gi1);
    k_combine<<<1, H>>>(p_gi1, p_gh1, h1_prev, p_h1, out + V + H);
    // output projection + log_softmax
    k_logits<<<(V + 15) / 16, 256>>>(out_w, out_b, out);
    k_lse_partial<<<RED_BLOCKS, 256>>>(out);
    k_lse_apply<<<(V + 1023) / 1024, 256>>>(out);
}

// round 6
// speedup vs baseline: 1.3228x; 1.1073x over previous
#include <cuda_runtime.h>
#include <cstdint>
#include <math.h>

#define V 50257
#define H 1024
#define L 128

// ---------------- scratch (device globals) ----------------
__device__ float g_attn_logits[L];
__device__ float g_attn_applied[H];
__device__ float g_x[H];
__device__ float g_gi0[3 * H];
__device__ float g_gh0[3 * H];
__device__ float g_gi1[3 * H];
__device__ float g_gh1[3 * H];
__device__ float g_h0[H];
__device__ float g_h1[H];
__device__ float g_red_max[128];
__device__ float g_red_sum[128];

// ---------------- helpers ----------------
__inline__ __device__ float warpReduceSum(float v) {
    #pragma unroll
    for (int o = 16; o > 0; o >>= 1) v += __shfl_down_sync(0xffffffffu, v, o);
    return v;
}
__inline__ __device__ float warpReduceMax(float v) {
    #pragma unroll
    for (int o = 16; o > 0; o >>= 1) v = fmaxf(v, __shfl_down_sync(0xffffffffu, v, o));
    return v;
}
__inline__ __device__ float blockReduceSum(float v, float* sh) {
    int lane = threadIdx.x & 31, wid = threadIdx.x >> 5;
    v = warpReduceSum(v);
    if (lane == 0) sh[wid] = v;
    __syncthreads();
    int nw = blockDim.x >> 5;
    v = (threadIdx.x < nw) ? sh[lane] : 0.f;
    if (wid == 0) v = warpReduceSum(v);
    return v;
}
__inline__ __device__ float blockReduceMax(float v, float* sh) {
    int lane = threadIdx.x & 31, wid = threadIdx.x >> 5;
    v = warpReduceMax(v);
    if (lane == 0) sh[wid] = v;
    __syncthreads();
    int nw = blockDim.x >> 5;
    v = (threadIdx.x < nw) ? sh[lane] : -INFINITY;
    if (wid == 0) v = warpReduceMax(v);
    return v;
}
__inline__ __device__ float dot4(float4 a, float4 b) {
    return a.x * b.x + a.y * b.y + a.z * b.z + a.w * b.w;
}
__inline__ __device__ void cp16(unsigned int saddr, const void* gptr) {
    asm volatile("cp.async.cg.shared.global [%0], [%1], 16;" :: "r"(saddr), "l"(gptr));
}
__inline__ __device__ void cp_commit_wait() {
    asm volatile("cp.async.commit_group;\ncp.async.wait_group 0;" ::: "memory");
}

// ================= async-GEMV building block =================
// Block = 256 threads (8 warps), each block handles 8 rows of width 1024.
// Weights streamed into 32KB SMEM via cp.async (2048x16B, 8 per thread);
// x register-resident (L2-hot). Warp w reduces row w.

// ---------------- K1: fused attn_logits + gh0 + gh1 -------------------------
// blocks [0,16): attn rows (width 2048, two passes)
// blocks [16,400): gh0 rows; blocks [400,784): gh1 rows
__global__ void __launch_bounds__(256) k_phase1(
        const long long* __restrict__ ids,
        const float* __restrict__ emb,
        const float* __restrict__ hidden,
        const float* __restrict__ attn_w,
        const float* __restrict__ attn_b,
        const float* __restrict__ w_hh0,
        const float* __restrict__ b_hh0,
        const float* __restrict__ w_hh1,
        const float* __restrict__ b_hh1) {
    __shared__ float4 sw[2048];   // 32KB
    int t = threadIdx.x, warp = t >> 5, lane = t & 31;
    unsigned int sbase = (unsigned int)__cvta_generic_to_shared(sw);
    int b = blockIdx.x;

    if (b < 16) {
        // attention rows: 8 rows per block, width 2H, split in two 1024 passes
        int row0 = b * 8;
        const float4* er = (const float4*)(emb + (size_t)ids[0] * H);
        const float4* h0 = (const float4*)hidden;
        float4 xv[8];
        // pass A: emb part
        #pragma unroll
        for (int i = 0; i < 8; i++) {
            int c = t + 256 * i;
            const char* g = (const char*)(attn_w + (size_t)(row0 + i) * (2 * H)) + (size_t)t * 16;
            cp16(sbase + (unsigned)c * 16, g);
        }
        #pragma unroll
        for (int i = 0; i < 8; i++) xv[i] = __ldg(&er[lane + 32 * i]);
        cp_commit_wait();
        __syncthreads();
        float s = 0.f;
        #pragma unroll
        for (int i = 0; i < 8; i++) s += dot4(sw[warp * 256 + lane + 32 * i], xv[i]);
        __syncthreads();
        // pass B: hidden part
        #pragma unroll
        for (int i = 0; i < 8; i++) {
            int c = t + 256 * i;
            const char* g = (const char*)(attn_w + (size_t)(row0 + i) * (2 * H) + H) + (size_t)t * 16;
            cp16(sbase + (unsigned)c * 16, g);
        }
        #pragma unroll
        for (int i = 0; i < 8; i++) xv[i] = __ldg(&h0[lane + 32 * i]);
        cp_commit_wait();
        __syncthreads();
        #pragma unroll
        for (int i = 0; i < 8; i++) s += dot4(sw[warp * 256 + lane + 32 * i], xv[i]);
        s = warpReduceSum(s);
        int row = row0 + warp;
        if (lane == 0) g_attn_logits[row] = s + attn_b[row];
    } else {
        bool is0 = (b < 16 + 384);
        int row0 = (is0 ? (b - 16) : (b - 400)) * 8;
        const float* wmat = is0 ? w_hh0 : w_hh1;
        const float* bias = is0 ? b_hh0 : b_hh1;
        const float4* hv4 = (const float4*)(is0 ? hidden : hidden + H);
        float* dst = is0 ? g_gh0 : g_gh1;
        #pragma unroll
        for (int i = 0; i < 8; i++) {
            int c = t + 256 * i;
            const char* g = (const char*)(wmat + (size_t)(row0 + i) * H) + (size_t)t * 16;
            cp16(sbase + (unsigned)c * 16, g);
        }
        float4 xv[8];
        #pragma unroll
        for (int i = 0; i < 8; i++) xv[i] = __ldg(&hv4[lane + 32 * i]);
        cp_commit_wait();
        __syncthreads();
        float s = 0.f;
        #pragma unroll
        for (int i = 0; i < 8; i++) s += dot4(sw[warp * 256 + lane + 32 * i], xv[i]);
        s = warpReduceSum(s);
        int row = row0 + warp;
        if (lane == 0) dst[row] = s + bias[row];
    }
}

// ---------------- K2: softmax (redundant per block) + attn_applied ----------
__global__ void k_softmax_applied(const float* __restrict__ enc,
                                  float* __restrict__ out) {
    __shared__ float sh[32];
    __shared__ float sM, sS;
    __shared__ float aw[L];
    int t = threadIdx.x;  // 128
    float v = g_attn_logits[t];
    float m = blockReduceMax(v, sh);
    if (t == 0) sM = m;
    __syncthreads();
    float e = expf(v - sM);
    __syncthreads();
    float s = blockReduceSum(e, sh);
    if (t == 0) sS = s;
    __syncthreads();
    float w = e / sS;
    aw[t] = w;
    if (blockIdx.x == 0) out[V + 2 * H + t] = w;
    __syncthreads();
    int h = blockIdx.x * 128 + t;
    float acc = 0.f;
    #pragma unroll 8
    for (int l = 0; l < L; l++) acc += aw[l] * enc[(size_t)l * H + h];
    g_attn_applied[h] = acc;
}

// ---------------- K3: comb + relu (width 2048, two passes) -------------------
__global__ void __launch_bounds__(256) k_comb(
        const long long* __restrict__ ids,
        const float* __restrict__ emb,
        const float* __restrict__ comb_w,
        const float* __restrict__ comb_b) {
    __shared__ float4 sw[2048];
    int t = threadIdx.x, warp = t >> 5, lane = t & 31;
    unsigned int sbase = (unsigned int)__cvta_generic_to_shared(sw);
    int row0 = blockIdx.x * 8;
    const float4* er = (const float4*)(emb + (size_t)ids[0] * H);
    const float4* ap = (const float4*)g_attn_applied;
    float4 xv[8];
    // pass A
    #pragma unroll
    for (int i = 0; i < 8; i++) {
        int c = t + 256 * i;
        const char* g = (const char*)(comb_w + (size_t)(row0 + i) * (2 * H)) + (size_t)t * 16;
        cp16(sbase + (unsigned)c * 16, g);
    }
    #pragma unroll
    for (int i = 0; i < 8; i++) xv[i] = __ldg(&er[lane + 32 * i]);
    cp_commit_wait();
    __syncthreads();
    float s = 0.f;
    #pragma unroll
    for (int i = 0; i < 8; i++) s += dot4(sw[warp * 256 + lane + 32 * i], xv[i]);
    __syncthreads();
    // pass B
    #pragma unroll
    for (int i = 0; i < 8; i++) {
        int c = t + 256 * i;
        const char* g = (const char*)(comb_w + (size_t)(row0 + i) * (2 * H) + H) + (size_t)t * 16;
        cp16(sbase + (unsigned)c * 16, g);
    }
    #pragma unroll
    for (int i = 0; i < 8; i++) xv[i] = __ldg(&ap[lane + 32 * i]);
    cp_commit_wait();
    __syncthreads();
    #pragma unroll
    for (int i = 0; i < 8; i++) s += dot4(sw[warp * 256 + lane + 32 * i], xv[i]);
    s = warpReduceSum(s);
    int j = row0 + warp;
    if (lane == 0) {
        float r = s + comb_b[j];
        g_x[j] = r > 0.f ? r : 0.f;
    }
}

// ---------------- K4/K6: gi = x @ w_ih^T + b_ih ------------------------------
__global__ void __launch_bounds__(256) k_gi(
        const float* __restrict__ xin,
        const float* __restrict__ w_ih,
        const float* __restrict__ b_ih,
        float* __restrict__ gi) {
    __shared__ float4 sw[2048];
    int t = threadIdx.x, warp = t >> 5, lane = t & 31;
    unsigned int sbase = (unsigned int)__cvta_generic_to_shared(sw);
    int row0 = blockIdx.x * 8;
    #pragma unroll
    for (int i = 0; i < 8; i++) {
        int c = t + 256 * i;
        const char* g = (const char*)(w_ih + (size_t)(row0 + i) * H) + (size_t)t * 16;
        cp16(sbase + (unsigned)c * 16, g);
    }
    const float4* x4 = (const float4*)xin;
    float4 xv[8];
    #pragma unroll
    for (int i = 0; i < 8; i++) xv[i] = __ldg(&x4[lane + 32 * i]);
    cp_commit_wait();
    __syncthreads();
    float s = 0.f;
    #pragma unroll
    for (int i = 0; i < 8; i++) s += dot4(sw[warp * 256 + lane + 32 * i], xv[i]);
    s = warpReduceSum(s);
    int row = row0 + warp;
    if (lane == 0) gi[row] = s + b_ih[row];
}

// ---------------- K5/K7: GRU combine ------------------------------------------
__global__ void k_combine(const float* __restrict__ gi,
                          const float* __restrict__ gh,
                          const float* __restrict__ hprev,
                          float* __restrict__ hnew,
                          float* __restrict__ out_hid) {
    int t = threadIdx.x;
    float r = 1.f / (1.f + expf(-(gi[t] + gh[t])));
    float z = 1.f / (1.f + expf(-(gi[H + t] + gh[H + t])));
    float n = tanhf(gi[2 * H + t] + r * gh[2 * H + t]);
    float h = (1.f - z) * n + z * hprev[t];
    hnew[t] = h;
    out_hid[t] = h;
}

// ---------------- K8: logits (2 rows/warp, 16 batched loads) ------------------
__global__ void __launch_bounds__(256) k_logits(
        const float* __restrict__ out_w,
        const float* __restrict__ out_b,
        float* __restrict__ logits) {
    int warp = threadIdx.x >> 5;
    int lane = threadIdx.x & 31;
    int j0 = (blockIdx.x * 8 + warp) * 2;
    if (j0 >= V) return;
    const float4* h = (const float4*)g_h1;
    float4 hv[8];
    #pragma unroll
    for (int i = 0; i < 8; i++) hv[i] = __ldg(&h[lane + 32 * i]);

    const float4* w0 = (const float4*)(out_w + (size_t)j0 * H);
    bool has1 = (j0 + 1) < V;
    const float4* w1 = (const float4*)(out_w + (size_t)(has1 ? j0 + 1 : j0) * H);

    float4 w0v[8], w1v[8];
    #pragma unroll
    for (int i = 0; i < 8; i++) w0v[i] = __ldcs(&w0[lane + 32 * i]);
    #pragma unroll
    for (int i = 0; i < 8; i++) w1v[i] = __ldcs(&w1[lane + 32 * i]);

    float s0 = 0.f, s1 = 0.f;
    #pragma unroll
    for (int i = 0; i < 8; i++) {
        s0 += dot4(w0v[i], hv[i]);
        s1 += dot4(w1v[i], hv[i]);
    }
    s0 = warpReduceSum(s0);
    s1 = warpReduceSum(s1);
    if (lane == 0) {
        logits[j0] = s0 + out_b[j0];
        if (has1) logits[j0 + 1] = s1 + out_b[j0 + 1];
    }
}

// ---------------- K9: per-block max/sumexp partials ----------------------------
#define RED_BLOCKS 128
__global__ void k_lse_partial(const float* __restrict__ logits) {
    __shared__ float sh[32];
    __shared__ float sM;
    const int chunk = (V + RED_BLOCKS - 1) / RED_BLOCKS;  // 393
    int start = blockIdx.x * chunk;
    int end = min(start + chunk, V);
    float m = -INFINITY;
    for (int i = start + threadIdx.x; i < end; i += blockDim.x)
        m = fmaxf(m, logits[i]);
    m = blockReduceMax(m, sh);
    if (threadIdx.x == 0) sM = m;
    __syncthreads();
    float M = sM;
    float s = 0.f;
    for (int i = start + threadIdx.x; i < end; i += blockDim.x)
        s += expf(logits[i] - M);
    __syncthreads();
    s = blockReduceSum(s, sh);
    if (threadIdx.x == 0) {
        g_red_max[blockIdx.x] = M;
        g_red_sum[blockIdx.x] = s;
    }
}

// ---------------- K10: reduce partials (redundant) + apply ---------------------
__global__ void k_lse_apply(float* __restrict__ logits) {
    __shared__ float sh[32];
    __shared__ float sM, sLogZ;
    int t = threadIdx.x;
    float m = (t < RED_BLOCKS) ? g_red_max[t] : -INFINITY;
    float M = blockReduceMax(m, sh);
    if (t == 0) sM = M;
    __syncthreads();
    M = sM;
    float s = (t < RED_BLOCKS) ? g_red_sum[t] * expf(g_red_max[t] - M) : 0.f;
    __syncthreads();
    s = blockReduceSum(s, sh);
    if (t == 0) sLogZ = M + logf(s);
    __syncthreads();
    float lz = sLogZ;
    int base = blockIdx.x * 1024 + t;
    #pragma unroll
    for (int k = 0; k < 4; k++) {
        int i = base + k * 256;
        if (i < V) logits[i] -= lz;
    }
}

// =================================================================================
extern "C" void kernel_launch(void* const* d_in, const int* in_sizes, int n_in,
                              void* d_out, int out_size) {
    const long long* input_ids = (const long long*)d_in[0];
    const float* hidden  = (const float*)d_in[1];
    const float* enc     = (const float*)d_in[2];
    const float* emb     = (const float*)d_in[3];
    const float* attn_w  = (const float*)d_in[4];
    const float* attn_b  = (const float*)d_in[5];
    const float* comb_w  = (const float*)d_in[6];
    const float* comb_b  = (const float*)d_in[7];
    const float* w_ih0   = (const float*)d_in[8];
    const float* w_hh0   = (const float*)d_in[9];
    const float* b_ih0   = (const float*)d_in[10];
    const float* b_hh0   = (const float*)d_in[11];
    const float* w_ih1   = (const float*)d_in[12];
    const float* w_hh1   = (const float*)d_in[13];
    const float* b_ih1   = (const float*)d_in[14];
    const float* b_hh1   = (const float*)d_in[15];
    const float* out_w   = (const float*)d_in[16];
    const float* out_b   = (const float*)d_in[17];

    float* out = (float*)d_out;

    const float* h0_prev = hidden;
    const float* h1_prev = hidden + H;

    float* p_x;   cudaGetSymbolAddress((void**)&p_x, g_x);
    float* p_h0;  cudaGetSymbolAddress((void**)&p_h0, g_h0);
    float* p_h1;  cudaGetSymbolAddress((void**)&p_h1, g_h1);
    float* p_gi0; cudaGetSymbolAddress((void**)&p_gi0, g_gi0);
    float* p_gh0; cudaGetSymbolAddress((void**)&p_gh0, g_gh0);
    float* p_gi1; cudaGetSymbolAddress((void**)&p_gi1, g_gi1);
    float* p_gh1; cudaGetSymbolAddress((void**)&p_gh1, g_gh1);

    // Phase 1: attention logits (16 blocks) + gh0 (384) + gh1 (384)
    k_phase1<<<16 + 2 * 384, 256>>>(input_ids, emb, hidden, attn_w, attn_b,
                                    w_hh0, b_hh0, w_hh1, b_hh1);
    k_softmax_applied<<<8, 128>>>(enc, out);
    k_comb<<<H / 8, 256>>>(input_ids, emb, comb_w, comb_b);
    k_gi<<<3 * H / 8, 256>>>(p_x, w_ih0, b_ih0, p_gi0);
    k_combine<<<1, H>>>(p_gi0, p_gh0, h0_prev, p_h0, out + V);
    k_gi<<<3 * H / 8, 256>>>(p_h0, w_ih1, b_ih1, p_gi1);
    k_combine<<<1, H>>>(p_gi1, p_gh1, h1_prev, p_h1, out + V + H);
    k_logits<<<(V + 15) / 16, 256>>>(out_w, out_b, out);
    k_lse_partial<<<RED_BLOCKS, 256>>>(out);
    k_lse_apply<<<(V + 1023) / 1024, 256>>>(out);
}

// round 7
// speedup vs baseline: 1.3513x; 1.0216x over previous
#include <cuda_runtime.h>
#include <cstdint>
#include <math.h>

#define V 50257
#define H 1024
#define L 128

// ---------------- scratch (device globals) ----------------
__device__ float g_attn_logits[L];
__device__ float g_attn_applied[H];
__device__ float g_x[H];
__device__ float g_gi0[3 * H];
__device__ float g_gh0[3 * H];
__device__ float g_gi1[3 * H];
__device__ float g_gh1[3 * H];
__device__ float g_h0[H];
__device__ float g_h1[H];
__device__ float g_red_max[128];
__device__ float g_red_sum[128];

// ---------------- helpers ----------------
__inline__ __device__ float warpReduceSum(float v) {
    #pragma unroll
    for (int o = 16; o > 0; o >>= 1) v += __shfl_down_sync(0xffffffffu, v, o);
    return v;
}
__inline__ __device__ float warpReduceMax(float v) {
    #pragma unroll
    for (int o = 16; o > 0; o >>= 1) v = fmaxf(v, __shfl_down_sync(0xffffffffu, v, o));
    return v;
}
__inline__ __device__ float blockReduceSum(float v, float* sh) {
    int lane = threadIdx.x & 31, wid = threadIdx.x >> 5;
    v = warpReduceSum(v);
    if (lane == 0) sh[wid] = v;
    __syncthreads();
    int nw = blockDim.x >> 5;
    v = (threadIdx.x < nw) ? sh[lane] : 0.f;
    if (wid == 0) v = warpReduceSum(v);
    return v;
}
__inline__ __device__ float blockReduceMax(float v, float* sh) {
    int lane = threadIdx.x & 31, wid = threadIdx.x >> 5;
    v = warpReduceMax(v);
    if (lane == 0) sh[wid] = v;
    __syncthreads();
    int nw = blockDim.x >> 5;
    v = (threadIdx.x < nw) ? sh[lane] : -INFINITY;
    if (wid == 0) v = warpReduceMax(v);
    return v;
}
__inline__ __device__ float dot4(float4 a, float4 b) {
    return a.x * b.x + a.y * b.y + a.z * b.z + a.w * b.w;
}

// ---------------- TMA bulk copy + mbarrier helpers ----------------
__inline__ __device__ void mbar_init(unsigned mbar) {
    asm volatile("mbarrier.init.shared.b64 [%0], 1;" :: "r"(mbar) : "memory");
}
__inline__ __device__ void mbar_expect_tx(unsigned mbar, unsigned bytes) {
    asm volatile("mbarrier.arrive.expect_tx.shared.b64 _, [%0], %1;"
                 :: "r"(mbar), "r"(bytes) : "memory");
}
__inline__ __device__ void bulk_g2s(unsigned dst, const void* src, unsigned bytes,
                                    unsigned mbar) {
    asm volatile(
        "cp.async.bulk.shared::cta.global.mbarrier::complete_tx::bytes [%0], [%1], %2, [%3];"
        :: "r"(dst), "l"(src), "r"(bytes), "r"(mbar) : "memory");
}
__inline__ __device__ void mbar_wait0(unsigned mbar) {
    asm volatile(
        "{\n\t"
        ".reg .pred P1;\n\t"
        "WAIT_LOOP_%=:\n\t"
        "mbarrier.try_wait.parity.acquire.cta.shared::cta.b64 P1, [%0], 0, 0x989680;\n\t"
        "@P1 bra.uni WAIT_DONE_%=;\n\t"
        "bra.uni WAIT_LOOP_%=;\n\t"
        "WAIT_DONE_%=:\n\t"
        "}"
        :: "r"(mbar) : "memory");
}

// ================= TMA-GEMV building blocks =================
// Block = 256 threads. One bulk TMA copy of 32KB of contiguous weight rows
// into SMEM; x is register-resident (L2-hot LDG, overlapped with TMA).

// ---------------- K1: fused attn_logits + gh0 + gh1 -------------------------
// blocks [0,32): attn (4 rows x 2048/blk); [32,416): gh0 (8x1024); [416,800): gh1
__global__ void __launch_bounds__(256) k_phase1(
        const long long* __restrict__ ids,
        const float* __restrict__ emb,
        const float* __restrict__ hidden,
        const float* __restrict__ attn_w,
        const float* __restrict__ attn_b,
        const float* __restrict__ w_hh0,
        const float* __restrict__ b_hh0,
        const float* __restrict__ w_hh1,
        const float* __restrict__ b_hh1) {
    __shared__ alignas(128) float4 sw[2048];   // 32KB
    __shared__ alignas(8) unsigned long long mbar_s;
    __shared__ float shpart[8];
    int t = threadIdx.x, warp = t >> 5, lane = t & 31;
    unsigned mbar = (unsigned)__cvta_generic_to_shared(&mbar_s);
    unsigned sdst = (unsigned)__cvta_generic_to_shared(sw);
    int b = blockIdx.x;

    if (t == 0) mbar_init(mbar);
    __syncthreads();

    if (b < 32) {
        int row0 = b * 4;  // 4 rows of width 2048
        if (t == 0) {
            mbar_expect_tx(mbar, 32768);
            bulk_g2s(sdst, attn_w + (size_t)row0 * (2 * H), 32768, mbar);
        }
        // warp handles row (warp>>1), half (warp&1)
        const float4* src = (warp & 1) ? (const float4*)hidden
                                       : (const float4*)(emb + (size_t)ids[0] * H);
        float4 xv[8];
        #pragma unroll
        for (int i = 0; i < 8; i++) xv[i] = __ldg(&src[lane + 32 * i]);
        mbar_wait0(mbar);
        float s = 0.f;
        #pragma unroll
        for (int i = 0; i < 8; i++) s += dot4(sw[warp * 256 + lane + 32 * i], xv[i]);
        s = warpReduceSum(s);
        if (lane == 0) shpart[warp] = s;
        __syncthreads();
        if (t < 4) g_attn_logits[row0 + t] = shpart[2 * t] + shpart[2 * t + 1] + attn_b[row0 + t];
    } else {
        bool is0 = (b < 32 + 384);
        int row0 = (is0 ? (b - 32) : (b - 416)) * 8;
        const float* wmat = is0 ? w_hh0 : w_hh1;
        const float* bias = is0 ? b_hh0 : b_hh1;
        const float4* hv4 = (const float4*)(is0 ? hidden : hidden + H);
        float* dst = is0 ? g_gh0 : g_gh1;
        if (t == 0) {
            mbar_expect_tx(mbar, 32768);
            bulk_g2s(sdst, wmat + (size_t)row0 * H, 32768, mbar);
        }
        float4 xv[8];
        #pragma unroll
        for (int i = 0; i < 8; i++) xv[i] = __ldg(&hv4[lane + 32 * i]);
        mbar_wait0(mbar);
        float s = 0.f;
        #pragma unroll
        for (int i = 0; i < 8; i++) s += dot4(sw[warp * 256 + lane + 32 * i], xv[i]);
        s = warpReduceSum(s);
        int row = row0 + warp;
        if (lane == 0) dst[row] = s + bias[row];
    }
}

// ---------------- K2: softmax (redundant per block) + attn_applied ----------
__global__ void k_softmax_applied(const float* __restrict__ enc,
                                  float* __restrict__ out) {
    __shared__ float sh[32];
    __shared__ float sM, sS;
    __shared__ float aw[L];
    int t = threadIdx.x;  // 128
    float v = g_attn_logits[t];
    float m = blockReduceMax(v, sh);
    if (t == 0) sM = m;
    __syncthreads();
    float e = expf(v - sM);
    __syncthreads();
    float s = blockReduceSum(e, sh);
    if (t == 0) sS = s;
    __syncthreads();
    float w = e / sS;
    aw[t] = w;
    if (blockIdx.x == 0) out[V + 2 * H + t] = w;
    __syncthreads();
    int h = blockIdx.x * 128 + t;
    float acc = 0.f;
    #pragma unroll 8
    for (int l = 0; l < L; l++) acc += aw[l] * enc[(size_t)l * H + h];
    g_attn_applied[h] = acc;
}

// ---------------- K3: comb + relu (4 rows x 2048 per block) ------------------
__global__ void __launch_bounds__(256) k_comb(
        const long long* __restrict__ ids,
        const float* __restrict__ emb,
        const float* __restrict__ comb_w,
        const float* __restrict__ comb_b) {
    __shared__ alignas(128) float4 sw[2048];
    __shared__ alignas(8) unsigned long long mbar_s;
    __shared__ float shpart[8];
    int t = threadIdx.x, warp = t >> 5, lane = t & 31;
    unsigned mbar = (unsigned)__cvta_generic_to_shared(&mbar_s);
    unsigned sdst = (unsigned)__cvta_generic_to_shared(sw);
    int row0 = blockIdx.x * 4;

    if (t == 0) mbar_init(mbar);
    __syncthreads();
    if (t == 0) {
        mbar_expect_tx(mbar, 32768);
        bulk_g2s(sdst, comb_w + (size_t)row0 * (2 * H), 32768, mbar);
    }
    const float4* src = (warp & 1) ? (const float4*)g_attn_applied
                                   : (const float4*)(emb + (size_t)ids[0] * H);
    float4 xv[8];
    #pragma unroll
    for (int i = 0; i < 8; i++) xv[i] = __ldg(&src[lane + 32 * i]);
    mbar_wait0(mbar);
    float s = 0.f;
    #pragma unroll
    for (int i = 0; i < 8; i++) s += dot4(sw[warp * 256 + lane + 32 * i], xv[i]);
    s = warpReduceSum(s);
    if (lane == 0) shpart[warp] = s;
    __syncthreads();
    if (t < 4) {
        float r = shpart[2 * t] + shpart[2 * t + 1] + comb_b[row0 + t];
        g_x[row0 + t] = r > 0.f ? r : 0.f;
    }
}

// ---------------- K4/K6: gi = x @ w_ih^T + b_ih (8 rows x 1024) --------------
__global__ void __launch_bounds__(256) k_gi(
        const float* __restrict__ xin,
        const float* __restrict__ w_ih,
        const float* __restrict__ b_ih,
        float* __restrict__ gi) {
    __shared__ alignas(128) float4 sw[2048];
    __shared__ alignas(8) unsigned long long mbar_s;
    int t = threadIdx.x, warp = t >> 5, lane = t & 31;
    unsigned mbar = (unsigned)__cvta_generic_to_shared(&mbar_s);
    unsigned sdst = (unsigned)__cvta_generic_to_shared(sw);
    int row0 = blockIdx.x * 8;

    if (t == 0) mbar_init(mbar);
    __syncthreads();
    if (t == 0) {
        mbar_expect_tx(mbar, 32768);
        bulk_g2s(sdst, w_ih + (size_t)row0 * H, 32768, mbar);
    }
    const float4* x4 = (const float4*)xin;
    float4 xv[8];
    #pragma unroll
    for (int i = 0; i < 8; i++) xv[i] = __ldg(&x4[lane + 32 * i]);
    mbar_wait0(mbar);
    float s = 0.f;
    #pragma unroll
    for (int i = 0; i < 8; i++) s += dot4(sw[warp * 256 + lane + 32 * i], xv[i]);
    s = warpReduceSum(s);
    int row = row0 + warp;
    if (lane == 0) gi[row] = s + b_ih[row];
}

// ---------------- K5/K7: GRU combine ------------------------------------------
__global__ void k_combine(const float* __restrict__ gi,
                          const float* __restrict__ gh,
                          const float* __restrict__ hprev,
                          float* __restrict__ hnew,
                          float* __restrict__ out_hid) {
    int t = threadIdx.x;
    float r = 1.f / (1.f + expf(-(gi[t] + gh[t])));
    float z = 1.f / (1.f + expf(-(gi[H + t] + gh[H + t])));
    float n = tanhf(gi[2 * H + t] + r * gh[2 * H + t]);
    float h = (1.f - z) * n + z * hprev[t];
    hnew[t] = h;
    out_hid[t] = h;
}

// ---------------- K8: logits (2 rows/warp, 16 batched loads) ------------------
__global__ void __launch_bounds__(256) k_logits(
        const float* __restrict__ out_w,
        const float* __restrict__ out_b,
        float* __restrict__ logits) {
    int warp = threadIdx.x >> 5;
    int lane = threadIdx.x & 31;
    int j0 = (blockIdx.x * 8 + warp) * 2;
    if (j0 >= V) return;
    const float4* h = (const float4*)g_h1;
    float4 hv[8];
    #pragma unroll
    for (int i = 0; i < 8; i++) hv[i] = __ldg(&h[lane + 32 * i]);

    const float4* w0 = (const float4*)(out_w + (size_t)j0 * H);
    bool has1 = (j0 + 1) < V;
    const float4* w1 = (const float4*)(out_w + (size_t)(has1 ? j0 + 1 : j0) * H);

    float4 w0v[8], w1v[8];
    #pragma unroll
    for (int i = 0; i < 8; i++) w0v[i] = __ldcs(&w0[lane + 32 * i]);
    #pragma unroll
    for (int i = 0; i < 8; i++) w1v[i] = __ldcs(&w1[lane + 32 * i]);

    float s0 = 0.f, s1 = 0.f;
    #pragma unroll
    for (int i = 0; i < 8; i++) {
        s0 += dot4(w0v[i], hv[i]);
        s1 += dot4(w1v[i], hv[i]);
    }
    s0 = warpReduceSum(s0);
    s1 = warpReduceSum(s1);
    if (lane == 0) {
        logits[j0] = s0 + out_b[j0];
        if (has1) logits[j0 + 1] = s1 + out_b[j0 + 1];
    }
}

// ---------------- K9: per-block max/sumexp partials ----------------------------
#define RED_BLOCKS 128
__global__ void k_lse_partial(const float* __restrict__ logits) {
    __shared__ float sh[32];
    __shared__ float sM;
    const int chunk = (V + RED_BLOCKS - 1) / RED_BLOCKS;  // 393
    int start = blockIdx.x * chunk;
    int end = min(start + chunk, V);
    float m = -INFINITY;
    for (int i = start + threadIdx.x; i < end; i += blockDim.x)
        m = fmaxf(m, logits[i]);
    m = blockReduceMax(m, sh);
    if (threadIdx.x == 0) sM = m;
    __syncthreads();
    float M = sM;
    float s = 0.f;
    for (int i = start + threadIdx.x; i < end; i += blockDim.x)
        s += expf(logits[i] - M);
    __syncthreads();
    s = blockReduceSum(s, sh);
    if (threadIdx.x == 0) {
        g_red_max[blockIdx.x] = M;
        g_red_sum[blockIdx.x] = s;
    }
}

// ---------------- K10: reduce partials (redundant) + apply ---------------------
__global__ void k_lse_apply(float* __restrict__ logits) {
    __shared__ float sh[32];
    __shared__ float sM, sLogZ;
    int t = threadIdx.x;
    float m = (t < RED_BLOCKS) ? g_red_max[t] : -INFINITY;
    float M = blockReduceMax(m, sh);
    if (t == 0) sM = M;
    __syncthreads();
    M = sM;
    float s = (t < RED_BLOCKS) ? g_red_sum[t] * expf(g_red_max[t] - M) : 0.f;
    __syncthreads();
    s = blockReduceSum(s, sh);
    if (t == 0) sLogZ = M + logf(s);
    __syncthreads();
    float lz = sLogZ;
    int base = blockIdx.x * 1024 + t;
    #pragma unroll
    for (int k = 0; k < 4; k++) {
        int i = base + k * 256;
        if (i < V) logits[i] -= lz;
    }
}

// =================================================================================
extern "C" void kernel_launch(void* const* d_in, const int* in_sizes, int n_in,
                              void* d_out, int out_size) {
    const long long* input_ids = (const long long*)d_in[0];
    const float* hidden  = (const float*)d_in[1];
    const float* enc     = (const float*)d_in[2];
    const float* emb     = (const float*)d_in[3];
    const float* attn_w  = (const float*)d_in[4];
    const float* attn_b  = (const float*)d_in[5];
    const float* comb_w  = (const float*)d_in[6];
    const float* comb_b  = (const float*)d_in[7];
    const float* w_ih0   = (const float*)d_in[8];
    const float* w_hh0   = (const float*)d_in[9];
    const float* b_ih0   = (const float*)d_in[10];
    const float* b_hh0   = (const float*)d_in[11];
    const float* w_ih1   = (const float*)d_in[12];
    const float* w_hh1   = (const float*)d_in[13];
    const float* b_ih1   = (const float*)d_in[14];
    const float* b_hh1   = (const float*)d_in[15];
    const float* out_w   = (const float*)d_in[16];
    const float* out_b   = (const float*)d_in[17];

    float* out = (float*)d_out;

    const float* h0_prev = hidden;
    const float* h1_prev = hidden + H;

    float* p_x;   cudaGetSymbolAddress((void**)&p_x, g_x);
    float* p_h0;  cudaGetSymbolAddress((void**)&p_h0, g_h0);
    float* p_h1;  cudaGetSymbolAddress((void**)&p_h1, g_h1);
    float* p_gi0; cudaGetSymbolAddress((void**)&p_gi0, g_gi0);
    float* p_gh0; cudaGetSymbolAddress((void**)&p_gh0, g_gh0);
    float* p_gi1; cudaGetSymbolAddress((void**)&p_gi1, g_gi1);
    float* p_gh1; cudaGetSymbolAddress((void**)&p_gh1, g_gh1);

    // Phase 1: attn (32 blocks, 4x2048) + gh0 (384, 8x1024) + gh1 (384)
    k_phase1<<<32 + 2 * 384, 256>>>(input_ids, emb, hidden, attn_w, attn_b,
                                    w_hh0, b_hh0, w_hh1, b_hh1);
    k_softmax_applied<<<8, 128>>>(enc, out);
    k_comb<<<H / 4, 256>>>(input_ids, emb, comb_w, comb_b);
    k_gi<<<3 * H / 8, 256>>>(p_x, w_ih0, b_ih0, p_gi0);
    k_combine<<<1, H>>>(p_gi0, p_gh0, h0_prev, p_h0, out + V);
    k_gi<<<3 * H / 8, 256>>>(p_h0, w_ih1, b_ih1, p_gi1);
    k_combine<<<1, H>>>(p_gi1, p_gh1, h1_prev, p_h1, out + V + H);
    k_logits<<<(V + 15) / 16, 256>>>(out_w, out_b, out);
    k_lse_partial<<<RED_BLOCKS, 256>>>(out);
    k_lse_apply<<<(V + 1023) / 1024, 256>>>(out);
}